// round 7
// baseline (speedup 1.0000x reference)
#include <cuda_runtime.h>
#include <cuda_bf16.h>

#define Hdim 512
#define Wdim 512
#define Qn 3
#define Pn 1024
#define Bn 64
#define JITTER 1e-6f

// Precomputed symmetrized spectrum: S_sym[p][ky*16+kx] / 256
__device__ float g_S[Pn * 256];

// ---------------------------------------------------------------------------
// Kernel A: build S per patch (separable Gaussians), then index-symmetrize:
//   S_sym[k] = (S[k] + S[(-k) mod 16]) / 2    (makes Xf*S exactly Hermitian)
// ---------------------------------------------------------------------------
__global__ __launch_bounds__(256) void make_S_kernel(
    const float* __restrict__ logits,
    const float* __restrict__ mu,
    const float* __restrict__ sigma)
{
    __shared__ float w[4];
    __shared__ float gy[6][16];
    __shared__ float gx[6][16];
    __shared__ float sAcc[256];

    const int p = blockIdx.x;
    const int t = threadIdx.x;

    if (t == 0) {
        const float l0 = logits[p * Qn + 0];
        const float l1 = logits[p * Qn + 1];
        const float l2 = logits[p * Qn + 2];
        const float mx = fmaxf(l0, fmaxf(l1, l2));
        const float e0 = expf(l0 - mx);
        const float e1 = expf(l1 - mx);
        const float e2 = expf(l2 - mx);
        const float inv = 1.0f / (e0 + e1 + e2);
        w[0] = e0 * inv; w[1] = e1 * inv; w[2] = e2 * inv;
    }
    if (t < 192) {
        const int axis = t / 96;
        const int rem  = t % 96;
        const int qs   = rem >> 4;
        const int k    = rem & 15;
        const int q    = qs >> 1;
        const int sgn  = qs & 1;
        const float f  = (float)(k < 8 ? k : k - 16) * (1.0f / 16.0f);
        const int base = (p * Qn + q) * 2;
        const float m  = mu[base + axis];
        const float s  = sigma[base + axis];
        const float d  = (sgn ? (f + m) : (f - m)) / s;
        const float v  = expf(-0.5f * d * d);
        if (axis == 0) gy[qs][k] = v; else gx[qs][k] = v;
    }
    __syncthreads();

    const int ky = t >> 4;
    const int kx = t & 15;
    float acc = 0.0f;
#pragma unroll
    for (int q = 0; q < Qn; ++q) {
        acc += w[q] * (gy[2 * q][ky] * gx[2 * q][kx] +
                       gy[2 * q + 1][ky] * gx[2 * q + 1][kx]);
    }
    sAcc[t] = acc;
    __syncthreads();

    const int tm = (((16 - ky) & 15) << 4) | ((16 - kx) & 15);
    const float ssym = 0.5f * (sAcc[t] + sAcc[tm]) + JITTER;
    g_S[p * 256 + t] = ssym * (1.0f / 256.0f);
}

// ---------------------------------------------------------------------------
// Fully unrolled 16-point complex FFT. DIR=-1 fwd, DIR=+1 inv (unnormalized).
// ---------------------------------------------------------------------------
template<int DIR>
__device__ __forceinline__ void fft16(float re[16], float im[16]) {
#define SWAPF(a,b) { float _t=re[a]; re[a]=re[b]; re[b]=_t; _t=im[a]; im[a]=im[b]; im[b]=_t; }
    SWAPF(1, 8) SWAPF(2, 4) SWAPF(3, 12) SWAPF(5, 10) SWAPF(7, 14) SWAPF(11, 13)
#undef SWAPF
    const float CT[8] = { 1.0f,  0.9238795325112867f,  0.7071067811865476f,  0.3826834323650898f,
                          0.0f, -0.3826834323650898f, -0.7071067811865476f, -0.9238795325112867f };
    const float ST[8] = { 0.0f,  0.3826834323650898f,  0.7071067811865476f,  0.9238795325112867f,
                          1.0f,  0.9238795325112867f,  0.7071067811865476f,  0.3826834323650898f };
#pragma unroll
    for (int s = 1; s <= 4; ++s) {
        const int len   = 1 << s;
        const int half  = len >> 1;
        const int tstep = 16 >> s;
#pragma unroll
        for (int i = 0; i < 16; i += len) {
#pragma unroll
            for (int j = 0; j < half; ++j) {
                const float c  = CT[j * tstep];
                const float sn = (float)DIR * ST[j * tstep];
                const int a = i + j;
                const int b = a + half;
                float br = re[b], bi = im[b];
                float tr = c * br - sn * bi;
                float ti = c * bi + sn * br;
                re[b] = re[a] - tr;
                im[b] = im[a] - ti;
                re[a] += tr;
                im[a] += ti;
            }
        }
    }
}

// ---------------------------------------------------------------------------
// Kernel B: block = one adjacent patch pair (A,B) x 16 batches.
// Round 7: x LDGs issued before S staging (MLP over startup), S staged
// transposed (float4 reads in phase 2), bias loaded directly from global
// in the epilogue (no smem round trip).
// ---------------------------------------------------------------------------
__global__ __launch_bounds__(256, 4) void patch_spectral_kernel(
    const float* __restrict__ x,
    const float* __restrict__ bias,
    float* __restrict__ y)
{
    __shared__ float2 colbuf[16][288];   // per group: stage (576 f) / strips (272 f2)
    __shared__ float  sSt[2][336];       // transposed S: sSt[h][kx*20+ky]

    const int pp = blockIdx.x & 511;     // patch-pair index
    const int bg = blockIdx.x >> 9;      // batch group (16 batches)
    const int t  = threadIdx.x;
    const int p0 = pp * 2;

    const int wrp = t >> 5;       // warp 0..7
    const int l   = t & 31;       // lane
    const int g0  = wrp * 2;      // two groups (batches) per warp
    const int py  = p0 >> 5;
    const int px0 = p0 & 31;

    float* ss = (float*)colbuf;   // flat stage view

    // ---- issue all x loads first (8-deep MLP over block startup) ----
    const int seg = l >> 3;
    const int c4  = (l & 7) * 4;
    float4 xr[8];
#pragma unroll
    for (int i = 0; i < 8; ++i) {
        const int q   = i * 4 + seg;
        const int gof = q >> 4;
        const int r   = q & 15;
        const int b   = bg * 16 + g0 + gof;
        xr[i] = *(const float4*)(x + (size_t)b * (Hdim * Wdim)
                                   + (size_t)(py * 16 + r) * Wdim
                                   + px0 * 16 + c4);
    }

    // ---- stage S transposed while x loads are in flight ----
    {
        const int ky = t >> 4;
        const int kx = t & 15;
#pragma unroll
        for (int hh = 0; hh < 2; ++hh)
            sSt[hh][kx * 20 + ky] = g_S[(p0 + hh) * 256 + t];
    }
    __syncthreads();

    // ---- stage x (coalesced registers -> smem) ----
#pragma unroll
    for (int i = 0; i < 8; ++i) {
        const int q   = i * 4 + seg;
        const int gof = q >> 4;
        const int r   = q & 15;
        *(float4*)(ss + (g0 + gof) * 576 + r * 36 + c4) = xr[i];
    }
    __syncwarp();

    const int g  = g0 + (l >> 4);  // this lane's group (batch)
    const int ln = l & 15;         // row / task index within group
    float2* buf = colbuf[g];
    float* srow = ss + g * 576 + ln * 36;

    float zr[16], zi[16];

    // ---- phase 1: read own row pair from stage, packed row FFT ----
#pragma unroll
    for (int qq = 0; qq < 4; ++qq) {
        float4 va = *(const float4*)(srow + qq * 4);
        float4 vb = *(const float4*)(srow + 16 + qq * 4);
        zr[qq*4+0]=va.x; zr[qq*4+1]=va.y; zr[qq*4+2]=va.z; zr[qq*4+3]=va.w;
        zi[qq*4+0]=vb.x; zi[qq*4+1]=vb.y; zi[qq*4+2]=vb.z; zi[qq*4+3]=vb.w;
    }
    fft16<-1>(zr, zi);

    // Hermitian unpack, store column strips
    buf[0 * 17 + ln]       = make_float2(zr[0], zr[8]);   // A: (X[r,0], X[r,8])
    buf[(8 + 0) * 17 + ln] = make_float2(zi[0], zi[8]);   // B
#pragma unroll
    for (int k = 1; k <= 7; ++k) {
        const int m = 16 - k;
        buf[k * 17 + ln]       = make_float2(0.5f * (zr[k] + zr[m]), 0.5f * (zi[k] - zi[m]));
        buf[(8 + k) * 17 + ln] = make_float2(0.5f * (zi[k] + zi[m]), 0.5f * (zr[m] - zr[k]));
    }
    __syncwarp();

    // ---- phase 2: column task (tile = ln>>3, tt = ln&7) ----
    {
        const int tile = ln >> 3;
        const int tt   = ln & 7;
        float2* strip = buf + ln * 17;
#pragma unroll
        for (int r = 0; r < 16; ++r) { float2 v = strip[r]; zr[r] = v.x; zi[r] = v.y; }

        fft16<-1>(zr, zi);

        const float* Sp = sSt[tile];
        if (tt == 0) {
            // packed real cols 0 & 8: S[ky,0]=Sp[ky], S[ky,8]=Sp[160+ky]
#pragma unroll
            for (int ky = 0; ky <= 8; ++ky) {
                const int m = (16 - ky) & 15;
                const float s0 = Sp[ky];
                const float s8 = Sp[160 + ky];
                const float c0r = 0.5f * (zr[ky] + zr[m]);
                const float c0i = 0.5f * (zi[ky] - zi[m]);
                const float c8r = 0.5f * (zi[ky] + zi[m]);
                const float c8i = 0.5f * (zr[m] - zr[ky]);
                const float ar = c0r * s0, ai = c0i * s0;
                const float br = c8r * s8, bi = c8i * s8;
                zr[ky] = ar - bi;  zi[ky] = ai + br;
                if (m != ky) { zr[m] = ar + bi; zi[m] = br - ai; }
            }
        } else {
            // contiguous transposed column: 4 x LDS.128
            const float4* Sc = (const float4*)(Sp + tt * 20);
#pragma unroll
            for (int q2 = 0; q2 < 4; ++q2) {
                const float4 s4 = Sc[q2];
                zr[q2*4+0] *= s4.x;  zi[q2*4+0] *= s4.x;
                zr[q2*4+1] *= s4.y;  zi[q2*4+1] *= s4.y;
                zr[q2*4+2] *= s4.z;  zi[q2*4+2] *= s4.z;
                zr[q2*4+3] *= s4.w;  zi[q2*4+3] *= s4.w;
            }
        }

        fft16<1>(zr, zi);

#pragma unroll
        for (int i = 0; i < 16; ++i) strip[i] = make_float2(zr[i], zi[i]);
    }
    __syncwarp();

    // ---- phase 3: Hermitian-extend W rows, packed inverse row FFT ----
    {
        float2 a0 = buf[0 * 17 + ln];
        float2 b0 = buf[(8 + 0) * 17 + ln];
        zr[0] = a0.x;  zi[0] = b0.x;
        zr[8] = a0.y;  zi[8] = b0.y;
#pragma unroll
        for (int k = 1; k <= 7; ++k) {
            float2 a = buf[k * 17 + ln];        // W_A[i,k]
            float2 c = buf[(8 + k) * 17 + ln];  // W_B[i,k]
            zr[k]      = a.x - c.y;   zi[k]      = a.y + c.x;   // W_A + i W_B
            zr[16 - k] = a.x + c.y;   zi[16 - k] = c.x - a.y;   // conj ext
        }
    }
    fft16<1>(zr, zi);

    // ---- epilogue: bias direct from global (L2-hot, contiguous per lane) ----
    {
        const float* bp = bias + p0 * 256 + ln * 16;
#pragma unroll
        for (int j = 0; j < 16; j += 4) {
            const float4 ba = *(const float4*)(bp + j);
            const float4 bb = *(const float4*)(bp + 256 + j);
            float4 oa, ob;
            oa.x = zr[j+0] + ba.x;  oa.y = zr[j+1] + ba.y;
            oa.z = zr[j+2] + ba.z;  oa.w = zr[j+3] + ba.w;
            ob.x = zi[j+0] + bb.x;  ob.y = zi[j+1] + bb.y;
            ob.z = zi[j+2] + bb.z;  ob.w = zi[j+3] + bb.w;
            *(float4*)(srow + j)      = oa;
            *(float4*)(srow + 16 + j) = ob;
        }
    }
    __syncwarp();

    // ---- staged coalesced store: 8 x STG.128, full sectors ----
#pragma unroll
    for (int i = 0; i < 8; ++i) {
        const int q   = i * 4 + seg;
        const int gof = q >> 4;
        const int r   = q & 15;
        const int gg  = g0 + gof;
        const int b   = bg * 16 + gg;
        float4 v = *(const float4*)(ss + gg * 576 + r * 36 + c4);
        *(float4*)(y + (size_t)b * (Hdim * Wdim)
                     + (size_t)(py * 16 + r) * Wdim
                     + px0 * 16 + c4) = v;
    }
}

extern "C" void kernel_launch(void* const* d_in, const int* in_sizes, int n_in,
                              void* d_out, int out_size)
{
    const float* x      = (const float*)d_in[0];
    const float* logits = (const float*)d_in[1];
    const float* mu     = (const float*)d_in[2];
    const float* sigma  = (const float*)d_in[3];
    const float* bias   = (const float*)d_in[4];
    float* y = (float*)d_out;

    make_S_kernel<<<Pn, 256>>>(logits, mu, sigma);
    patch_spectral_kernel<<<2048, 256>>>(x, bias, y);
}